// round 9
// baseline (speedup 1.0000x reference)
#include <cuda_runtime.h>
#include <cuda_fp16.h>
#include <math.h>
#include <stdint.h>

// Problem dims
#define T_DIM 512
#define B_DIM 32
#define E_DIM 512
#define H_DIM 2048

// Tiling: CTA = 64 threads (2 warps, 1M x 2N), warp tile 64x48, CTA tile 64x96
#define HC  32          // h channels per CTA
#define NT  96          // GEMM N = 3*HC (z|f|o)
#define MT  64          // t-chunk (GEMM M)
#define KC  32          // K elems per smem chunk (fp16 -> 64B rows, SW64)
#define NKC 16          // K chunks per t-chunk (512/32)
#define NTC 8           // t-chunks (512/64)
#define NCH (NTC * NKC) // 128 chunks total

#define ACT_STRIDE 104  // act row stride in halves (208B)

// ---- smem layout (bytes) ----
#define SM_A    0                    // 2 x 4096  (A stages, fp16 SW64, 64B rows)
#define SM_B    8192                 // 2 x 6144  (W stages, fp16 SW64, 64B rows)
#define SM_ACT  20480                // 64 x 104 x 2 = 13312 (fp16)
#define SM_BIAS 33792                // 96 floats = 384
#define SM_SEGA 34176                // 2 x 32 floats = 256
#define SM_SEGB 34432                // 2 x 32 floats = 256
#define SMEM_BYTES 34688             // x6 CTAs = 208128 <= 228KB

#define SWZ64(x) ((x) ^ (((x) >> 3) & 0x30))

// fp16 scratch (static device allocations — allowed)
__device__ __half g_sentH[B_DIM * T_DIM * E_DIM];   // (B,T,E) fp16
__device__ __half g_wH[3 * H_DIM * E_DIM];          // (3H,E)  fp16

// ---------------- helpers ----------------
__device__ __forceinline__ uint32_t smem_u32(const void* p) {
    uint32_t a;
    asm("{ .reg .u64 t; cvta.to.shared.u64 t, %1; cvt.u32.u64 %0, t; }" : "=r"(a) : "l"(p));
    return a;
}
__device__ __forceinline__ float tanh_hw(float x) {
    float y; asm("tanh.approx.f32 %0, %1;" : "=f"(y) : "f"(x)); return y;
}
__device__ __forceinline__ float sigmoid_hw(float x) {
    return fmaf(0.5f, tanh_hw(0.5f * x), 0.5f);
}
__device__ __forceinline__ void cp_async16(uint32_t dst, const void* src) {
    uint64_t g; asm("cvta.to.global.u64 %0, %1;" : "=l"(g) : "l"(src));
    asm volatile("cp.async.cg.shared.global [%0], [%1], 16;" :: "r"(dst), "l"(g) : "memory");
}
__device__ __forceinline__ void ldsm4(uint32_t* r, uint32_t addr) {
    asm volatile("ldmatrix.sync.aligned.m8n8.x4.shared.b16 {%0,%1,%2,%3}, [%4];"
                 : "=r"(r[0]), "=r"(r[1]), "=r"(r[2]), "=r"(r[3]) : "r"(addr));
}
__device__ __forceinline__ void mma_f16(float* c, const uint32_t* a, const uint32_t* b) {
    asm volatile(
        "mma.sync.aligned.m16n8k16.row.col.f32.f16.f16.f32 "
        "{%0,%1,%2,%3}, {%4,%5,%6,%7}, {%8,%9}, {%0,%1,%2,%3};"
        : "+f"(c[0]), "+f"(c[1]), "+f"(c[2]), "+f"(c[3])
        : "r"(a[0]), "r"(a[1]), "r"(a[2]), "r"(a[3]), "r"(b[0]), "r"(b[1]));
}

// ---------- merged prepass: fp32 -> fp16; sent also transposed (T,B,E)->(B,T,E) ----------
#define SENT_F4 (T_DIM * B_DIM * E_DIM / 4)   // 2,097,152
#define W_F4    (3 * H_DIM * E_DIM / 4)       //   786,432
__global__ void __launch_bounds__(256) prep_all(const float* __restrict__ sent,
                                                const float* __restrict__ W) {
    int li = blockIdx.x * 256 + threadIdx.x;
    if (li < SENT_F4) {
        const float4 v = ((const float4*)sent)[li];
        int e4 = li & 127;
        int b  = (li >> 7) & 31;
        int t  = li >> 12;
        __half2* dst = (__half2*)(g_sentH + ((size_t)(b * T_DIM + t) * E_DIM + e4 * 4));
        dst[0] = __floats2half2_rn(v.x, v.y);
        dst[1] = __floats2half2_rn(v.z, v.w);
    } else if (li < SENT_F4 + W_F4) {
        int wi = li - SENT_F4;
        const float4 v = ((const float4*)W)[wi];
        __half2* dst = (__half2*)g_wH + (size_t)wi * 2;
        dst[0] = __floats2half2_rn(v.x, v.y);
        dst[1] = __floats2half2_rn(v.z, v.w);
    }
}

// -------- main fused kernel: 64 threads, 2 warps (1M x 2N), warp tile 64x48, occ 6 --------
__global__ void __launch_bounds__(64, 6)
qrnn_f16_kernel(const float* __restrict__ bias, float* __restrict__ out)
{
    extern __shared__ char smem[];
    const uint32_t sb = smem_u32(smem);
    const int tid = threadIdx.x;
    const int bb  = blockIdx.y;
    const int h0  = blockIdx.x * HC;
    const int lane = tid & 31;
    const int wid  = tid >> 5;        // 0..1
    const int g  = lane >> 2;
    const int tg = lane & 3;
    const int n_base = wid * 48;      // warp's 6 n-frags of 8

    float*  sbias = (float*)(smem + SM_BIAS);
    __half* act   = (__half*)(smem + SM_ACT);
    float*  segA  = (float*)(smem + SM_SEGA);   // [2][32]
    float*  segB  = (float*)(smem + SM_SEGB);   // [2][32]
    for (int i = tid; i < 96; i += 64)
        sbias[i] = bias[(i >> 5) * H_DIM + h0 + (i & 31)];

    const __half* Asrc = g_sentH + (size_t)bb * (T_DIM * E_DIM);

    // per-lane ldmatrix address components (m8n8.x4 lane->row mapping)
    const int am = lane >> 3;
    const int a_row_in = (am & 1) * 8 + (lane & 7);   // row within m16 frag
    const int a_colb16 = (am >> 1) * 16;              // k-half byte offset
    const int b_row_in = (am >> 1) * 8 + (lane & 7);  // n within n16 pair
    const int b_colb16 = (am & 1) * 16;

    // stage chunk (tc, kc) into buffer buf (64 threads, SW64 64B rows)
    auto stage = [&](int tc, int kc, int buf) {
        const __half* ab = Asrc + (size_t)(tc * MT) * E_DIM + kc * KC;
        const uint32_t aB = sb + SM_A + buf * 4096;
#pragma unroll
        for (int i = 0; i < 4; i++) {                 // A: 64 rows x 64B = 256 x 16B
            int l = i * 64 + tid;
            int row = l >> 2, c = l & 3;
            cp_async16(aB + (uint32_t)SWZ64(row * 64 + c * 16), ab + (size_t)row * E_DIM + c * 8);
        }
        const uint32_t bB = sb + SM_B + buf * 6144;
#pragma unroll
        for (int i = 0; i < 6; i++) {                 // B: 96 rows x 64B = 384 x 16B
            int l = i * 64 + tid;
            int n = l >> 2, c = l & 3;
            int wrow = (n >> 5) * H_DIM + h0 + (n & 31);
            cp_async16(bB + (uint32_t)SWZ64(n * 64 + c * 16),
                       g_wH + (size_t)wrow * E_DIM + kc * KC + c * 8);
        }
        asm volatile("cp.async.commit_group;" ::: "memory");
    };

    // scan: warp wid owns t-segment [32*wid, 32*wid+32); lane owns channel h=lane
    float c_carry = 0.0f;        // replicated across warps
    float m_state = -INFINITY;

    stage(0, 0, 0);

    for (int tc = 0; tc < NTC; tc++) {
        float acc[4][6][4];
#pragma unroll
        for (int mf = 0; mf < 4; mf++)
#pragma unroll
            for (int nf = 0; nf < 6; nf++)
#pragma unroll
                for (int q = 0; q < 4; q++) acc[mf][nf][q] = 0.0f;

        for (int kc = 0; kc < NKC; kc++) {
            const int ch  = tc * NKC + kc;
            const int buf = ch & 1;

            __syncthreads();   // alt buffer's MMA readers (chunk ch-1) done
            if (ch + 1 < NCH) {
                stage((ch + 1) >> 4, (ch + 1) & 15, (ch + 1) & 1);
                asm volatile("cp.async.wait_group 1;" ::: "memory");
            } else {
                asm volatile("cp.async.wait_group 0;" ::: "memory");
            }
            __syncthreads();   // chunk ch fully staged

            const uint32_t aB = sb + SM_A + buf * 4096;
            const uint32_t bB = sb + SM_B + buf * 6144;
#pragma unroll
            for (int ks = 0; ks < 2; ks++) {     // 2 k16-steps over KC=32
                uint32_t a[4][4];
#pragma unroll
                for (int mf = 0; mf < 4; mf++) {
                    int row  = mf * 16 + a_row_in;
                    int colb = ks * 32 + a_colb16;
                    ldsm4(a[mf], aB + (uint32_t)SWZ64(row * 64 + colb));
                }
                uint32_t b[6][2];
#pragma unroll
                for (int p = 0; p < 3; p++) {
                    int nrow = n_base + p * 16 + b_row_in;
                    int colb = ks * 32 + b_colb16;
                    uint32_t r[4];
                    ldsm4(r, bB + (uint32_t)SWZ64(nrow * 64 + colb));
                    b[2 * p][0] = r[0];     b[2 * p][1] = r[1];
                    b[2 * p + 1][0] = r[2]; b[2 * p + 1][1] = r[3];
                }
#pragma unroll
                for (int mf = 0; mf < 4; mf++)
#pragma unroll
                    for (int nf = 0; nf < 6; nf++)
                        mma_f16(acc[mf][nf], a[mf], b[nf]);
            }
        }

        // ---- epilogue: bias + activation -> act (fp16 half2) ----
#pragma unroll
        for (int mf = 0; mf < 4; mf++) {
            int r0 = mf * 16 + g;
#pragma unroll
            for (int nf = 0; nf < 6; nf++) {
                int j   = n_base + nf * 8 + tg * 2;
                int grp = j >> 5;
#pragma unroll
                for (int rr = 0; rr < 2; rr++) {
                    int row  = r0 + rr * 8;
                    float v0 = acc[mf][nf][rr * 2 + 0] + sbias[j];
                    float v1 = acc[mf][nf][rr * 2 + 1] + sbias[j + 1];
                    if (grp == 0) { v0 = tanh_hw(v0);    v1 = tanh_hw(v1); }
                    else          { v0 = sigmoid_hw(v0); v1 = sigmoid_hw(v1); }
                    *(__half2*)(act + row * ACT_STRIDE + j) = __floats2half2_rn(v0, v1);
                }
            }
        }
        __syncthreads();

        // ---- parallel segmented scan: warp = 32-t segment, lane = channel ----
        const int t0s = wid * 32;
        float Aseg = 1.0f, Bseg = 0.0f;
#pragma unroll 8
        for (int i = 0; i < 32; i++) {
            const __half* rowp = act + (t0s + i) * ACT_STRIDE;
            float z = __half2float(rowp[lane]);
            float f = __half2float(rowp[32 + lane]);
            float a = 1.0f - f;
            Aseg *= a;
            Bseg = fmaf(a, Bseg, f * z);
        }
        segA[wid * 32 + lane] = Aseg;
        segB[wid * 32 + lane] = Bseg;
        __syncthreads();

        // c at entry of my segment
        float c = c_carry;
        if (wid == 1) c = fmaf(segA[lane], c, segB[lane]);
        // pass 2: walk my 32 t's
#pragma unroll 8
        for (int i = 0; i < 32; i++) {
            const __half* rowp = act + (t0s + i) * ACT_STRIDE;
            float z = __half2float(rowp[lane]);
            float f = __half2float(rowp[32 + lane]);
            float o = __half2float(rowp[64 + lane]);
            c = fmaf(f, z - c, c);                 // c = f*z + (1-f)*c
            m_state = fmaxf(m_state, o * c);
        }
        // advance carry over the whole chunk (replicated in both warps)
#pragma unroll
        for (int s = 0; s < 2; s++)
            c_carry = fmaf(segA[s * 32 + lane], c_carry, segB[s * 32 + lane]);
        // next chunk's k-loop barriers order these reads before seg overwrite
    }

    // final: max across the 2 segment-warps of each channel
    __syncthreads();                    // seg reads done; reuse segA as staging
    segA[wid * 32 + lane] = m_state;
    __syncthreads();
    if (wid == 0) {
        float r = fmaxf(m_state, segA[32 + lane]);
        out[bb * H_DIM + h0 + lane] = r;
    }
}

extern "C" void kernel_launch(void* const* d_in, const int* in_sizes, int n_in,
                              void* d_out, int out_size)
{
    (void)in_sizes; (void)n_in; (void)out_size;
    const float* sent = (const float*)d_in[0];   // (T,B,E) fp32
    const float* W    = (const float*)d_in[2];   // (3H,E)  fp32
    const float* bias = (const float*)d_in[3];   // (3H)    fp32
    float* out = (float*)d_out;                  // (B,H)   fp32

    cudaFuncSetAttribute(qrnn_f16_kernel, cudaFuncAttributeMaxDynamicSharedMemorySize, SMEM_BYTES);

    prep_all<<<(SENT_F4 + W_F4 + 255) / 256, 256>>>(sent, W);
    qrnn_f16_kernel<<<dim3(H_DIM / HC, B_DIM), 64, SMEM_BYTES>>>(bias, out);
}